// round 1
// baseline (speedup 1.0000x reference)
#include <cuda_runtime.h>
#include <cstdint>

#define BATCH 16384
#define NN 32
#define LD 36   // row pitch in floats: 36*4=144B -> conflict-free float4 row access

// ---------------- device globals (no allocation allowed) ----------------
__device__ double g_bce_sum;
__device__ double g_mask_sum;
__device__ double g_phys_sum;
__device__ float  g_td [NN * BATCH];   // tridiagonal d[i], transposed layout [i][b]
__device__ float  g_te2[NN * BATCH];   // subdiagonal squared e[i]^2, [i][b]

__device__ __forceinline__ float warp_sum(float x) {
#pragma unroll
    for (int o = 16; o > 0; o >>= 1) x += __shfl_xor_sync(0xffffffffu, x, o);
    return x;
}

__global__ void zero_kernel() {
    g_bce_sum = 0.0; g_mask_sum = 0.0; g_phys_sum = 0.0;
}

// ---------------- BCE kernel: HBM-bound streaming reduction ----------------
__global__ __launch_bounds__(256) void bce_kernel(
    const float4* __restrict__ pred, const float4* __restrict__ tgt,
    const float*  __restrict__ mask)
{
    const int total4 = BATCH * 256;   // (32*32)/4 float4 per batch
    float sb = 0.f, sm = 0.f;
    for (int id = blockIdx.x * blockDim.x + threadIdx.x; id < total4;
         id += gridDim.x * blockDim.x) {
        int base = id << 2;           // flat element index
        int b    = base >> 10;
        int rem  = base & 1023;
        int i    = rem >> 5;
        int j    = rem & 31;          // multiple of 4
        float  mi  = mask[(b << 5) + i];
        float4 mj  = *reinterpret_cast<const float4*>(mask + (b << 5) + j);
        float4 p   = pred[id];
        float4 t   = tgt[id];
        // target is exactly 0.0 or 1.0: bce = -log(t ? p : 1-p)
        float a0 = (t.x > 0.5f) ? p.x : 1.f - p.x;
        float a1 = (t.y > 0.5f) ? p.y : 1.f - p.y;
        float a2 = (t.z > 0.5f) ? p.z : 1.f - p.z;
        float a3 = (t.w > 0.5f) ? p.w : 1.f - p.w;
        float b0 = -__logf(a0);
        float b1 = -__logf(a1);
        float b2 = -__logf(a2);
        float b3 = -__logf(a3);
        sb += mi * (mj.x * b0 + mj.y * b1 + mj.z * b2 + mj.w * b3);
        sm += mi * (mj.x + mj.y + mj.z + mj.w);
    }
    sb = warp_sum(sb); sm = warp_sum(sm);
    __shared__ float rb[8], rm[8];
    int w = threadIdx.x >> 5, l = threadIdx.x & 31;
    if (l == 0) { rb[w] = sb; rm[w] = sm; }
    __syncthreads();
    if (w == 0) {
        sb = (l < (int)(blockDim.x >> 5)) ? rb[l] : 0.f;
        sm = (l < (int)(blockDim.x >> 5)) ? rm[l] : 0.f;
        sb = warp_sum(sb); sm = warp_sum(sm);
        if (l == 0) {
            atomicAdd(&g_bce_sum,  (double)sb);
            atomicAdd(&g_mask_sum, (double)sm);
        }
    }
}

// ---------------- Householder tridiagonalization: one warp per matrix ----------------
__global__ __launch_bounds__(128) void tridiag_kernel(const float* __restrict__ pred)
{
    __shared__ __align__(16) float sS[4][NN * LD];
    __shared__ __align__(16) float sv[4][NN];
    __shared__ __align__(16) float sq[4][NN];

    const int warp = threadIdx.x >> 5;
    const int lane = threadIdx.x & 31;
    const int b    = (blockIdx.x << 2) + warp;

    float* S = sS[warp];
    const float* P = pred + (size_t)b * 1024;

    // load full pred matrix, coalesced: S[i][j] = pred[i][j]
#pragma unroll
    for (int i = 0; i < NN; i++) S[i * LD + lane] = P[(i << 5) + lane];
    __syncwarp();

    // row sums D (row = lane), vectorized, conflict-free (144B pitch)
    float Dr;
    {
        const float4* row = reinterpret_cast<const float4*>(S + lane * LD);
        float4 acc = row[0];
#pragma unroll
        for (int i4 = 1; i4 < 8; i4++) {
            float4 r = row[i4];
            acc.x += r.x; acc.y += r.y; acc.z += r.z; acc.w += r.w;
        }
        Dr = (acc.x + acc.y) + (acc.z + acc.w);
    }
    const float jit  = 1e-5f + (float)lane * (9.0e-5f / 31.0f);
    const float dval = Dr + jit - S[lane * LD + lane];
    __syncwarp();

    // Symmetrize (JAX eigvalsh symmetrize_input=True): M_off = (A + A^T)/2.
    // Lane r owns pair set {(r,c), (c,r)} for c > r: no cross-lane write hazards.
#pragma unroll
    for (int t = 1; t < NN; t++) {
        int c = lane + t;
        if (c < NN) {
            float a  = S[lane * LD + c];
            float bb = S[c * LD + lane];
            float av = 0.5f * (a + bb);
            S[lane * LD + c] = av;
            S[c * LD + lane] = av;
        }
    }
    __syncwarp();

    // negate off-diagonals, set diagonal = D + jitter - pred_ii (lane = column)
#pragma unroll
    for (int i = 0; i < NN; i++) {
        float v = S[i * LD + lane];
        S[i * LD + lane] = (i == lane) ? dval : -v;
    }
    __syncwarp();

    // Householder tridiagonalization
    float myd = 0.f, mye2 = 0.f;
    float* vb = sv[warp];
    float* qb = sq[warp];

    for (int k = 0; k < NN - 2; k++) {
        float xi    = (lane > k) ? S[lane * LD + k] : 0.f;
        float sigma = warp_sum(xi * xi);
        float dk    = S[k * LD + k];
        float x1    = __shfl_sync(0xffffffffu, xi, k + 1);
        float nrm   = sqrtf(sigma);
        float alpha = (x1 >= 0.f) ? -nrm : nrm;   // resulting e[k]
        if (lane == k) { myd = dk; mye2 = sigma; } // e[k]^2 == sigma exactly

        float vi  = (lane == (k + 1)) ? (x1 - alpha) : xi;  // zero for lane<=k
        float vtv = warp_sum(vi * vi);
        float tau = (vtv > 0.f) ? 2.0f / vtv : 0.f;
        vb[lane] = vi;
        __syncwarp();

        const int i40 = (k + 1) >> 2;  // aligned start; vb/qb are zero below k+1
        // p_j = tau * (A v)_j, using row `lane` (matrix kept symmetric)
        float pj = 0.f;
        {
            const float4* row4 = reinterpret_cast<const float4*>(S + lane * LD);
            const float4* vb4  = reinterpret_cast<const float4*>(vb);
            for (int i4 = i40; i4 < 8; i4++) {
                float4 a = row4[i4]; float4 vv = vb4[i4];
                pj += a.x * vv.x; pj += a.y * vv.y;
                pj += a.z * vv.z; pj += a.w * vv.w;
            }
        }
        pj *= tau;
        if (lane <= k) pj = 0.f;
        float pv = warp_sum(pj * vi);
        float qj = fmaf(-0.5f * tau * pv, vi, pj);
        qb[lane] = qj;
        __syncwarp();

        // A <- A - v q^T - q v^T  (row `lane`, vectorized)
        {
            float4* w4 = reinterpret_cast<float4*>(S + lane * LD);
            const float4* vb4 = reinterpret_cast<const float4*>(vb);
            const float4* qb4 = reinterpret_cast<const float4*>(qb);
            for (int i4 = i40; i4 < 8; i4++) {
                float4 a = w4[i4]; float4 vv = vb4[i4]; float4 qq = qb4[i4];
                a.x -= vi * qq.x + qj * vv.x;
                a.y -= vi * qq.y + qj * vv.y;
                a.z -= vi * qq.z + qj * vv.z;
                a.w -= vi * qq.w + qj * vv.w;
                w4[i4] = a;
            }
        }
        __syncwarp();
    }

    if (lane == NN - 2) {
        myd = S[(NN - 2) * LD + (NN - 2)];
        float e = S[(NN - 1) * LD + (NN - 2)];
        mye2 = e * e;
    }
    if (lane == NN - 1) {
        myd = S[(NN - 1) * LD + (NN - 1)];
        mye2 = 0.f;
    }
    g_td [lane * BATCH + b] = myd;
    g_te2[lane * BATCH + b] = mye2;
}

// ---------------- lambda_2 via Sturm-sequence bisection: one thread per matrix ----------------
__global__ __launch_bounds__(256) void lambda2_kernel(float* __restrict__ out)
{
    const int b = blockIdx.x * blockDim.x + threadIdx.x;

    float d[NN], e2[NN - 1];
#pragma unroll
    for (int i = 0; i < NN; i++)     d[i]  = g_td [i * BATCH + b];   // coalesced
#pragma unroll
    for (int i = 0; i < NN - 1; i++) e2[i] = g_te2[i * BATCH + b];

    // Gershgorin bounds on the tridiagonal
    float lo = 1e30f, hi = -1e30f;
#pragma unroll
    for (int i = 0; i < NN; i++) {
        float r = 0.f;
        if (i > 0)      r += sqrtf(e2[i - 1]);
        if (i < NN - 1) r += sqrtf(e2[i]);
        lo = fminf(lo, d[i] - r);
        hi = fmaxf(hi, d[i] + r);
    }

    // bisection: boundary of {x : #eigs < x >= 2} is lambda_2
    for (int it = 0; it < 34; ++it) {
        float x   = 0.5f * (lo + hi);
        int   cnt = 0;
        float q   = d[0] - x;
        cnt += (q < 0.f);
#pragma unroll
        for (int i = 1; i < NN; i++) {
            if (q == 0.f) q = -1e-30f;
            q = d[i] - x - __fdividef(e2[i - 1], q);
            cnt += (q < 0.f);
        }
        if (cnt >= 2) hi = x; else lo = x;
    }
    float l2 = 0.5f * (lo + hi);
    out[2 + b] = l2;

    // physics loss accumulation: relu(0.1 - lambda2)
    float rl = fmaxf(0.1f - l2, 0.f);
    rl = warp_sum(rl);
    __shared__ float red[8];
    int w = threadIdx.x >> 5, l = threadIdx.x & 31;
    if (l == 0) red[w] = rl;
    __syncthreads();
    if (w == 0) {
        rl = (l < 8) ? red[l] : 0.f;
        rl = warp_sum(rl);
        if (l == 0) atomicAdd(&g_phys_sum, (double)rl);
    }
}

__global__ void finalize_kernel(float* __restrict__ out)
{
    double ms = g_mask_sum;
    if (ms < 1.0) ms = 1.0;
    out[0] = (float)(g_bce_sum / ms);
    out[1] = (float)(g_phys_sum / (double)BATCH);
}

// ---------------- entry point ----------------
extern "C" void kernel_launch(void* const* d_in, const int* in_sizes, int n_in,
                              void* d_out, int out_size)
{
    const float* pred = (const float*)d_in[0];
    const float* tgt  = (const float*)d_in[1];
    const float* mask = (const float*)d_in[2];
    float* out = (float*)d_out;

    zero_kernel<<<1, 1>>>();
    bce_kernel<<<2048, 256>>>((const float4*)pred, (const float4*)tgt, mask);
    tridiag_kernel<<<BATCH / 4, 128>>>(pred);
    lambda2_kernel<<<BATCH / 256, 256>>>(out);
    finalize_kernel<<<1, 1>>>(out);
}

// round 3
// speedup vs baseline: 1.1646x; 1.1646x over previous
#include <cuda_runtime.h>
#include <cstdint>

#define BATCH 16384
#define NN 32
#define LD 36   // row pitch: 144B -> conflict-free float4 row access

__device__ double g_bce_sum;
__device__ double g_mask_sum;
__device__ double g_phys_sum;

__device__ __forceinline__ float warp_sum(float x) {
#pragma unroll
    for (int o = 16; o > 0; o >>= 1) x += __shfl_xor_sync(0xffffffffu, x, o);
    return x;
}
__device__ __forceinline__ float warp_min(float x) {
#pragma unroll
    for (int o = 16; o > 0; o >>= 1) x = fminf(x, __shfl_xor_sync(0xffffffffu, x, o));
    return x;
}
__device__ __forceinline__ float warp_max(float x) {
#pragma unroll
    for (int o = 16; o > 0; o >>= 1) x = fmaxf(x, __shfl_xor_sync(0xffffffffu, x, o));
    return x;
}

__global__ void zero_kernel() {
    g_bce_sum = 0.0; g_mask_sum = 0.0; g_phys_sum = 0.0;
}

// One warp per matrix: BCE partial + symmetrized Laplacian build +
// Householder tridiagonalization + lane-parallel multisection Sturm bisection.
__global__ __launch_bounds__(128) void fused_kernel(
    const float* __restrict__ pred, const float* __restrict__ tgt,
    const float* __restrict__ mask, float* __restrict__ out)
{
    __shared__ __align__(16) float sS[4][NN * LD];
    __shared__ __align__(16) float sv[4][NN];
    __shared__ __align__(16) float sq[4][NN];
    __shared__ float red_b[4], red_m[4], red_p[4];

    const int warp = threadIdx.x >> 5;
    const int lane = threadIdx.x & 31;
    const int b    = (blockIdx.x << 2) + warp;

    float* S = sS[warp];
    const float* P = pred + (size_t)b * 1024;
    const float* T = tgt  + (size_t)b * 1024;

    // ---- load pred matrix (coalesced) ----
#pragma unroll
    for (int i = 0; i < NN; i++) S[i * LD + lane] = P[(i << 5) + lane];
    __syncwarp();

    // ---- BCE partial (uses raw pred in S + streaming tgt) ----
    float mj   = mask[(b << 5) + lane];
    float cntm = warp_sum(mj);            // number of active nodes
    float smask = cntm * cntm;            // sum of mask_2d for this matrix
    float sb = 0.f;
#pragma unroll
    for (int i = 0; i < NN; i++) {
        float mi = __shfl_sync(0xffffffffu, mj, i);
        float t  = T[(i << 5) + lane];
        float p  = S[i * LD + lane];
        float a  = (t > 0.5f) ? p : 1.0f - p;   // target is exactly {0,1}
        sb += (mi * mj) * (-__logf(a));
    }
    sb = warp_sum(sb);

    // ---- row sums D (original pred), vectorized conflict-free ----
    float Dr;
    {
        const float4* row = reinterpret_cast<const float4*>(S + lane * LD);
        float4 acc = row[0];
#pragma unroll
        for (int i4 = 1; i4 < 8; i4++) {
            float4 r = row[i4];
            acc.x += r.x; acc.y += r.y; acc.z += r.z; acc.w += r.w;
        }
        Dr = (acc.x + acc.y) + (acc.z + acc.w);
    }
    const float jit  = 1e-5f + (float)lane * (9.0e-5f / 31.0f);
    const float dval = Dr + jit - S[lane * LD + lane];
    __syncwarp();

    // ---- symmetrize (eigvalsh symmetrize_input): pair owner = lower lane ----
#pragma unroll
    for (int t = 1; t < NN; t++) {
        int c = lane + t;
        if (c < NN) {
            float a  = S[lane * LD + c];
            float bb = S[c * LD + lane];
            float av = 0.5f * (a + bb);
            S[lane * LD + c] = av;
            S[c * LD + lane] = av;
        }
    }
    __syncwarp();

    // ---- negate off-diag, set diagonal ----
#pragma unroll
    for (int i = 0; i < NN; i++) {
        float v = S[i * LD + lane];
        S[i * LD + lane] = (i == lane) ? dval : -v;
    }
    __syncwarp();

    // ---- Householder tridiagonalization (lane-predicated) ----
    float myd = 0.f, mye2 = 0.f;
    float* vb = sv[warp];
    float* qb = sq[warp];

    for (int k = 0; k < NN - 2; k++) {
        float xi    = (lane > k) ? S[lane * LD + k] : 0.f;
        float sigma = warp_sum(xi * xi);
        float dk    = S[k * LD + k];
        float x1    = __shfl_sync(0xffffffffu, xi, k + 1);
        float nrm   = sqrtf(sigma);
        float alpha = (x1 >= 0.f) ? -nrm : nrm;      // e[k] value
        if (lane == k) { myd = dk; mye2 = sigma; }   // e[k]^2 == sigma exactly

        float vi    = (lane == (k + 1)) ? (x1 - alpha) : xi;
        // v^T v = 2*(sigma - x1*alpha)  ->  tau = 2/v^Tv = 1/(sigma - x1*alpha)
        float denom = sigma - x1 * alpha;
        float tau   = (denom > 0.f) ? __fdividef(1.0f, denom) : 0.f;
        vb[lane] = vi;
        __syncwarp();

        const int i40 = (k + 1) >> 2;
        float pj = 0.f;
        if (lane > k) {
            const float4* row4 = reinterpret_cast<const float4*>(S + lane * LD);
            const float4* vb4  = reinterpret_cast<const float4*>(vb);
            for (int i4 = i40; i4 < 8; i4++) {
                float4 a = row4[i4]; float4 vv = vb4[i4];
                pj += a.x * vv.x; pj += a.y * vv.y;
                pj += a.z * vv.z; pj += a.w * vv.w;
            }
            pj *= tau;
        }
        float pv = warp_sum(pj * vi);
        float qj = fmaf(-0.5f * tau * pv, vi, pj);
        qb[lane] = qj;
        __syncwarp();

        if (lane > k) {
            float4* w4 = reinterpret_cast<float4*>(S + lane * LD);
            const float4* vb4 = reinterpret_cast<const float4*>(vb);
            const float4* qb4 = reinterpret_cast<const float4*>(qb);
            for (int i4 = i40; i4 < 8; i4++) {
                float4 a = w4[i4]; float4 vv = vb4[i4]; float4 qq = qb4[i4];
                a.x -= vi * qq.x + qj * vv.x;
                a.y -= vi * qq.y + qj * vv.y;
                a.z -= vi * qq.z + qj * vv.z;
                a.w -= vi * qq.w + qj * vv.w;
                w4[i4] = a;
            }
        }
        __syncwarp();
    }

    if (lane == NN - 2) {
        myd = S[(NN - 2) * LD + (NN - 2)];
        float e = S[(NN - 1) * LD + (NN - 2)];
        mye2 = e * e;
    }
    if (lane == NN - 1) {
        myd = S[(NN - 1) * LD + (NN - 1)];
        mye2 = 0.f;
    }

    // ---- publish tridiagonal to smem (reuse vb/qb), then multisection ----
    vb[lane] = myd;    // d[i]
    qb[lane] = mye2;   // e[i]^2 (coupling i <-> i+1), qb[31] = 0
    __syncwarp();

    // Gershgorin bounds
    float er  = sqrtf(mye2);
    float erp = __shfl_up_sync(0xffffffffu, er, 1);
    if (lane == 0) erp = 0.f;
    float rad = er + erp;
    float lo = warp_min(myd - rad) - 1e-3f;
    float hi = warp_max(myd + rad) + 1e-3f;

    // 33-section: lane l probes x_l, interval shrinks 33x per iteration
    const float inv33 = 1.0f / 33.0f;
    for (int it = 0; it < 6; it++) {
        float w = hi - lo;
        float x = fmaf(w, (float)(lane + 1) * inv33, lo);
        int cnt = 0;
        float q = vb[0] - x;
        cnt += (q < 0.f);
#pragma unroll
        for (int i = 1; i < NN; i++) {
            if (q == 0.f) q = -1e-30f;
            q = vb[i] - x - __fdividef(qb[i - 1], q);
            cnt += (q < 0.f);
        }
        unsigned m = __ballot_sync(0xffffffffu, cnt >= 2);
        if (m == 0u) {
            lo = fmaf(w, 32.0f * inv33, lo);
        } else {
            int j = __ffs(m) - 1;                      // first lane with cnt>=2
            float nhi = fmaf(w, (float)(j + 1) * inv33, lo);
            float nlo = (j == 0) ? lo : fmaf(w, (float)j * inv33, lo);
            hi = nhi; lo = nlo;
        }
    }
    float l2 = 0.5f * (lo + hi);

    // ---- outputs + block reduction for the three scalars ----
    if (lane == 0) {
        out[2 + b] = l2;
        red_b[warp] = sb;
        red_m[warp] = smask;
        red_p[warp] = fmaxf(0.1f - l2, 0.f);
    }
    __syncthreads();
    if (threadIdx.x == 0) {
        atomicAdd(&g_bce_sum,  (double)(red_b[0] + red_b[1] + red_b[2] + red_b[3]));
        atomicAdd(&g_mask_sum, (double)(red_m[0] + red_m[1] + red_m[2] + red_m[3]));
        atomicAdd(&g_phys_sum, (double)(red_p[0] + red_p[1] + red_p[2] + red_p[3]));
    }
}

__global__ void finalize_kernel(float* __restrict__ out)
{
    double ms = g_mask_sum;
    if (ms < 1.0) ms = 1.0;
    out[0] = (float)(g_bce_sum / ms);
    out[1] = (float)(g_phys_sum / (double)BATCH);
}

extern "C" void kernel_launch(void* const* d_in, const int* in_sizes, int n_in,
                              void* d_out, int out_size)
{
    const float* pred = (const float*)d_in[0];
    const float* tgt  = (const float*)d_in[1];
    const float* mask = (const float*)d_in[2];
    float* out = (float*)d_out;

    zero_kernel<<<1, 1>>>();
    fused_kernel<<<BATCH / 4, 128>>>(pred, tgt, mask, out);
    finalize_kernel<<<1, 1>>>(out);
}

// round 7
// speedup vs baseline: 1.5003x; 1.2882x over previous
#include <cuda_runtime.h>
#include <cstdint>

#define BATCH 16384
#define NN 32
#define NBLK (BATCH / 4)   // 4096 blocks, 4 warps (matrices) each

__device__ float        g_partial[NBLK * 3];
__device__ unsigned int g_count = 0;

__device__ __forceinline__ float warp_sum(float x) {
#pragma unroll
    for (int o = 16; o > 0; o >>= 1) x += __shfl_xor_sync(0xffffffffu, x, o);
    return x;
}
__device__ __forceinline__ float warp_min(float x) {
#pragma unroll
    for (int o = 16; o > 0; o >>= 1) x = fminf(x, __shfl_xor_sync(0xffffffffu, x, o));
    return x;
}
__device__ __forceinline__ float warp_max(float x) {
#pragma unroll
    for (int o = 16; o > 0; o >>= 1) x = fmaxf(x, __shfl_xor_sync(0xffffffffu, x, o));
    return x;
}

// One warp per matrix. Matrix lives in registers (lane = row).
__global__ __launch_bounds__(128, 6) void fused_kernel(
    const float4* __restrict__ pred4, const float4* __restrict__ tgt4,
    const float*  __restrict__ mask,  float* __restrict__ out)
{
    __shared__ __align__(16) float s_tr[4][NN * 33];  // transpose / tridiag scratch
    __shared__ __align__(16) float s_v [4][NN];
    __shared__ __align__(16) float s_q [4][NN];
    __shared__ float s_red[4][3];
    __shared__ float s_fr[3][4];
    __shared__ bool  s_last;

    const int warp = threadIdx.x >> 5;
    const int lane = threadIdx.x & 31;
    const int b    = (blockIdx.x << 2) + warp;

    float* tr = s_tr[warp];
    float* vb = s_v [warp];
    float* qb = s_q [warp];

    // ---- load own pred row into registers ----
    float a[NN];
    {
        const float4* prow = pred4 + (size_t)b * 256 + lane * 8;
#pragma unroll
        for (int j4 = 0; j4 < 8; j4++) {
            float4 v = prow[j4];
            a[4*j4+0] = v.x; a[4*j4+1] = v.y; a[4*j4+2] = v.z; a[4*j4+3] = v.w;
        }
    }
    float Dr = 0.f;
#pragma unroll
    for (int j = 0; j < NN; j++) Dr += a[j];

    // stage row to smem (33-pitch, conflict-free) for transpose + diag pick;
    // stage mask into vb for broadcast reads
    float m = mask[(b << 5) + lane];
    vb[lane] = m;
#pragma unroll
    for (int j = 0; j < NN; j++) tr[lane * 33 + j] = a[j];
    __syncwarp();

    // ---- BCE partial: row `lane`, tgt streamed, pred from regs ----
    float sb = 0.f;
    {
        const float4* trow = tgt4 + (size_t)b * 256 + lane * 8;
        const float4* m4   = (const float4*)vb;
#pragma unroll
        for (int j4 = 0; j4 < 8; j4++) {
            float4 t  = trow[j4];
            float4 mm = m4[j4];
            float p0 = a[4*j4+0], p1 = a[4*j4+1], p2 = a[4*j4+2], p3 = a[4*j4+3];
            float x0 = (t.x > 0.5f) ? p0 : 1.f - p0;
            float x1 = (t.y > 0.5f) ? p1 : 1.f - p1;
            float x2 = (t.z > 0.5f) ? p2 : 1.f - p2;
            float x3 = (t.w > 0.5f) ? p3 : 1.f - p3;
            sb += mm.x * (-__logf(x0)) + mm.y * (-__logf(x1))
                + mm.z * (-__logf(x2)) + mm.w * (-__logf(x3));
        }
        sb *= m;   // m_i factor for this row
    }
    sb = warp_sum(sb);
    float cntm  = warp_sum(m);
    float smask = cntm * cntm;

    // ---- build symmetrized Laplacian in registers ----
    const float jit  = 1e-5f + (float)lane * (9.0e-5f / 31.0f);
    float pii  = tr[lane * 33 + lane];
    float dval = Dr + jit - pii;
#pragma unroll
    for (int j = 0; j < NN; j++) {
        float c = tr[j * 33 + lane];                 // A[j][lane] (transpose)
        a[j] = (j == lane) ? dval : -0.5f * (a[j] + c);
    }
    __syncwarp();   // mask reads done; vb reused for Householder v

    // ---- Householder tridiagonalization, fully unrolled, register-resident ----
    float myd = 0.f, mye2 = 0.f;
#pragma unroll
    for (int k = 0; k < NN - 2; k++) {
        float x  = a[k];                              // A[lane][k], const reg index
        float xi = (lane > k) ? x : 0.f;
        float sigma = warp_sum(xi * xi);
        float x1 = __shfl_sync(0xffffffffu, xi, k + 1);
        float nrm   = sqrtf(sigma);
        float alpha = (x1 >= 0.f) ? -nrm : nrm;       // e[k]
        if (lane == k) { myd = x; mye2 = sigma; }     // d[k], e[k]^2

        float vi    = (lane == (k + 1)) ? (x1 - alpha) : xi;  // masked for lane<=k
        float denom = sigma - x1 * alpha;
        float tau   = (denom > 0.f) ? __fdividef(1.0f, denom) : 0.f;
        vb[lane] = vi;
        __syncwarp();

        const float4* vb4 = (const float4*)vb;
        float pj = 0.f;
#pragma unroll
        for (int j4 = (k + 1) >> 2; j4 < 8; j4++) {   // vb zero below k+1
            float4 vv = vb4[j4];
            pj += a[4*j4+0] * vv.x + a[4*j4+1] * vv.y
                + a[4*j4+2] * vv.z + a[4*j4+3] * vv.w;
        }
        pj = (lane > k) ? tau * pj : 0.f;             // mask q support
        float pv = warp_sum(pj * vi);
        float qj = fmaf(-0.5f * tau * pv, vi, pj);
        qb[lane] = qj;
        __syncwarp();

        const float4* qb4 = (const float4*)qb;
#pragma unroll
        for (int j4 = (k + 1) >> 2; j4 < 8; j4++) {
            float4 vv = vb4[j4];
            float4 qq = qb4[j4];
            a[4*j4+0] = fmaf(-vi, qq.x, fmaf(-qj, vv.x, a[4*j4+0]));
            a[4*j4+1] = fmaf(-vi, qq.y, fmaf(-qj, vv.y, a[4*j4+1]));
            a[4*j4+2] = fmaf(-vi, qq.z, fmaf(-qj, vv.z, a[4*j4+2]));
            a[4*j4+3] = fmaf(-vi, qq.w, fmaf(-qj, vv.w, a[4*j4+3]));
        }
        __syncwarp();   // before next iteration's vb overwrite
    }
    if (lane == NN - 2) {
        myd = a[NN - 2];
        float e = a[NN - 1];
        mye2 = e * e;
    }
    if (lane == NN - 1) { myd = a[NN - 1]; mye2 = 0.f; }

    // ---- publish tridiagonal, Sturm 33-section for lambda_2 ----
    tr[lane]      = myd;
    tr[NN + lane] = mye2;
    __syncwarp();

    float er  = sqrtf(mye2);
    float erp = __shfl_up_sync(0xffffffffu, er, 1);
    if (lane == 0) erp = 0.f;
    float rad = er + erp;
    float lo = warp_min(myd - rad) - 1e-3f;
    float hi = warp_max(myd + rad) + 1e-3f;

    const float inv33 = 1.0f / 33.0f;
    for (int it = 0; it < 6; it++) {
        float w = hi - lo;
        float xx = fmaf(w, (float)(lane + 1) * inv33, lo);
        int cnt = 0;
        float q = tr[0] - xx;
        cnt += (q < 0.f);
#pragma unroll
        for (int i = 1; i < NN; i++) {
            if (q == 0.f) q = -1e-30f;
            q = tr[i] - xx - __fdividef(tr[NN + i - 1], q);
            cnt += (q < 0.f);
        }
        unsigned mm = __ballot_sync(0xffffffffu, cnt >= 2);
        if (mm == 0u) {
            lo = fmaf(w, 32.0f * inv33, lo);
        } else {
            int j = __ffs(mm) - 1;
            float nhi = fmaf(w, (float)(j + 1) * inv33, lo);
            float nlo = (j == 0) ? lo : fmaf(w, (float)j * inv33, lo);
            hi = nhi; lo = nlo;
        }
    }
    float lam2 = 0.5f * (lo + hi);

    if (lane == 0) {
        out[2 + b] = lam2;
        s_red[warp][0] = sb;
        s_red[warp][1] = smask;
        s_red[warp][2] = fmaxf(0.1f - lam2, 0.f);
    }
    __syncthreads();

    // ---- grid-wide scalar reduction via last-block pattern ----
    if (threadIdx.x == 0) {
        float r0 = s_red[0][0] + s_red[1][0] + s_red[2][0] + s_red[3][0];
        float r1 = s_red[0][1] + s_red[1][1] + s_red[2][1] + s_red[3][1];
        float r2 = s_red[0][2] + s_red[1][2] + s_red[2][2] + s_red[3][2];
        g_partial[blockIdx.x * 3 + 0] = r0;
        g_partial[blockIdx.x * 3 + 1] = r1;
        g_partial[blockIdx.x * 3 + 2] = r2;
        __threadfence();
        unsigned v = atomicInc(&g_count, NBLK - 1);   // self-wrapping counter
        s_last = (v == NBLK - 1);
    }
    __syncthreads();

    if (s_last) {
        float r0 = 0.f, r1 = 0.f, r2 = 0.f;
        for (int i = threadIdx.x; i < NBLK; i += 128) {
            r0 += g_partial[3 * i + 0];
            r1 += g_partial[3 * i + 1];
            r2 += g_partial[3 * i + 2];
        }
        r0 = warp_sum(r0); r1 = warp_sum(r1); r2 = warp_sum(r2);
        int w2 = threadIdx.x >> 5, l2 = threadIdx.x & 31;
        if (l2 == 0) { s_fr[0][w2] = r0; s_fr[1][w2] = r1; s_fr[2][w2] = r2; }
        __syncthreads();
        if (threadIdx.x == 0) {
            float b0 = s_fr[0][0] + s_fr[0][1] + s_fr[0][2] + s_fr[0][3];
            float m0 = s_fr[1][0] + s_fr[1][1] + s_fr[1][2] + s_fr[1][3];
            float p0 = s_fr[2][0] + s_fr[2][1] + s_fr[2][2] + s_fr[2][3];
            if (m0 < 1.f) m0 = 1.f;
            out[0] = b0 / m0;
            out[1] = p0 / (float)BATCH;
        }
    }
}

extern "C" void kernel_launch(void* const* d_in, const int* in_sizes, int n_in,
                              void* d_out, int out_size)
{
    const float* pred = (const float*)d_in[0];
    const float* tgt  = (const float*)d_in[1];
    const float* mask = (const float*)d_in[2];
    float* out = (float*)d_out;

    fused_kernel<<<NBLK, 128>>>((const float4*)pred, (const float4*)tgt, mask, out);
}